// round 14
// baseline (speedup 1.0000x reference)
#include <cuda_runtime.h>
#include <cuda_bf16.h>

// PositionalEncoding: out[pos,2i]=sin(pos*w_i), out[pos,2i+1]=cos(pos*w_i),
// w_i = 10000^{-i/512}, d_model=1024, seq_len = out_size/1024. X unused.
//
// R13: at the chip write-acceptance floor (~2400 B/cyc; eight variants
// within noise of 7.4-7.9us, L2 pinned 36-39%). Run-to-run noise measured
// at +/-0.35us (identical source: 7.42 vs 7.78). Last untested lever:
// __stcg (L1-bypass stores) — L1 has read 41-43% every round, above L2;
// if any residual is L1tex write-queue occupancy, .cg reclaims it.
// Config otherwise = best measured (rows=4, grid=2048, dual rotation
// chains, STG.128).
//
// Math (verified 6.8e-5 rel err): seed angle = fp32 product pos*w (same
// rounding as the JAX ref), 2-term Cody-Waite mod-2pi (both FMAs exact,
// residual ~2e-7 rad) + MUFU __sincosf; two independent rotation chains
// (even/odd rows) stepping by double angle 2w (4 FMA/row, depth 2).

#define D_MODEL 1024
#define THREADS 256                    // thread t owns pair cols 2t, 2t+1
#define ROWS_PER_BLOCK 4
#define ROW_F4  (D_MODEL / 4)          // 256 float4 per row

#define NEG_K2    (-0.02595256324130752f)   // -log2(10000)/512
#define INV_2PI   (0.15915494309189535f)
#define TWO_PI_HI (6.28125f)                // exact in 9 mantissa bits
#define TWO_PI_LO (0.0019353071795864769f)  // 2pi - TWO_PI_HI

__device__ __forceinline__ void sincos_big(float theta, float* s, float* c) {
    // theta in [0, ~8200): 2-term Cody-Waite reduction mod 2pi, then MUFU.
    float n = rintf(theta * INV_2PI);
    float r = fmaf(-n, TWO_PI_HI, theta);
    r = fmaf(-n, TWO_PI_LO, r);
    __sincosf(r, s, c);
}

__global__ __launch_bounds__(THREADS, 8)
void pe_kernel(float4* __restrict__ out, int seq_len) {
    const int t = threadIdx.x;

    // Inverse frequencies (accuracy-critical: each via its own exp2f).
    const float w0 = exp2f((float)(2 * t)     * NEG_K2);
    const float w1 = exp2f((float)(2 * t + 1) * NEG_K2);

    const int row0 = blockIdx.x * ROWS_PER_BLOCK;
    if (row0 >= seq_len) return;

    // Chain A seed: even rows (fp32 angle product, same as reference).
    float sA0, cA0, sA1, cA1;
    sincos_big((float)row0 * w0, &sA0, &cA0);
    sincos_big((float)row0 * w1, &sA1, &cA1);

    // 1-row step (w <= 1 rad): MUFU path.
    float sw0, cw0, sw1, cw1;
    __sincosf(w0, &sw0, &cw0);
    __sincosf(w1, &sw1, &cw1);

    // Chain B seed = chain A rotated by one row.
    float sB0 = fmaf(sA0, cw0,  cA0 * sw0);
    float cB0 = fmaf(cA0, cw0, -sA0 * sw0);
    float sB1 = fmaf(sA1, cw1,  cA1 * sw1);
    float cB1 = fmaf(cA1, cw1, -sA1 * sw1);

    // 2-row step via double-angle: sin2w = 2 sw cw, cos2w = 1 - 2 sw^2.
    const float s20 = 2.0f * sw0 * cw0;
    const float c20 = fmaf(-2.0f * sw0, sw0, 1.0f);
    const float s21 = 2.0f * sw1 * cw1;
    const float c21 = fmaf(-2.0f * sw1, sw1, 1.0f);

    float4* p = out + (size_t)row0 * ROW_F4 + t;

    if (row0 + ROWS_PER_BLOCK <= seq_len) {
        #pragma unroll
        for (int r = 0; r < ROWS_PER_BLOCK / 2; r++) {
            __stcg(p,          make_float4(sA0, cA0, sA1, cA1));  // even row
            __stcg(p + ROW_F4, make_float4(sB0, cB0, sB1, cB1));  // odd row
            p += 2 * ROW_F4;
            // Rotate both chains by 2 rows — fully independent FMA trees.
            float nsA0 = fmaf(sA0, c20,  cA0 * s20);
            float ncA0 = fmaf(cA0, c20, -sA0 * s20);
            float nsA1 = fmaf(sA1, c21,  cA1 * s21);
            float ncA1 = fmaf(cA1, c21, -sA1 * s21);
            float nsB0 = fmaf(sB0, c20,  cB0 * s20);
            float ncB0 = fmaf(cB0, c20, -sB0 * s20);
            float nsB1 = fmaf(sB1, c21,  cB1 * s21);
            float ncB1 = fmaf(cB1, c21, -sB1 * s21);
            sA0 = nsA0; cA0 = ncA0; sA1 = nsA1; cA1 = ncA1;
            sB0 = nsB0; cB0 = ncB0; sB1 = nsB1; cB1 = ncB1;
        }
    } else {
        // Generic tail (seq_len not divisible by ROWS_PER_BLOCK).
        const int rows = seq_len - row0;
        for (int r = 0; r < rows; r += 2) {
            __stcg(p, make_float4(sA0, cA0, sA1, cA1));
            if (r + 1 < rows) __stcg(p + ROW_F4, make_float4(sB0, cB0, sB1, cB1));
            p += 2 * ROW_F4;
            float nsA0 = fmaf(sA0, c20,  cA0 * s20);
            float ncA0 = fmaf(cA0, c20, -sA0 * s20);
            float nsA1 = fmaf(sA1, c21,  cA1 * s21);
            float ncA1 = fmaf(cA1, c21, -sA1 * s21);
            float nsB0 = fmaf(sB0, c20,  cB0 * s20);
            float ncB0 = fmaf(cB0, c20, -sB0 * s20);
            float nsB1 = fmaf(sB1, c21,  cB1 * s21);
            float ncB1 = fmaf(cB1, c21, -sB1 * s21);
            sA0 = nsA0; cA0 = ncA0; sA1 = nsA1; cA1 = ncA1;
            sB0 = nsB0; cB0 = ncB0; sB1 = nsB1; cB1 = ncB1;
        }
    }
}

extern "C" void kernel_launch(void* const* d_in, const int* in_sizes, int n_in,
                              void* d_out, int out_size) {
    (void)d_in; (void)in_sizes; (void)n_in;
    const int seq_len = out_size / D_MODEL;    // 8192
    float4* out = (float4*)d_out;

    const int grid = (seq_len + ROWS_PER_BLOCK - 1) / ROWS_PER_BLOCK;  // 2048
    pe_kernel<<<grid, THREADS>>>(out, seq_len);
}

// round 15
// speedup vs baseline: 1.1365x; 1.1365x over previous
#include <cuda_runtime.h>
#include <cuda_bf16.h>

// PositionalEncoding: out[pos,2i]=sin(pos*w_i), out[pos,2i+1]=cos(pos*w_i),
// w_i = 10000^{-i/512}, d_model=1024, seq_len = out_size/1024. X unused.
//
// FINAL (R14). Nine structurally distinct variants (STG.128/STG.256/
// cp.async.bulk/__stcs/__stcg, occ 36-77%, compute 4x range, grids
// 512-8192) all land at 7.4-7.9us kernel dur with L2 pinned 36-39% =>
// the kernel sits on the chip's byte-level write-acceptance floor
// (~2400 B/cyc, path-independent). Floor = 33.5MB => ~7.3us; best
// measured = 7.42us (this config). This version keeps the best config
// (rows=4, grid=2048, dual rotation chains, plain STG.128) and
// front-batches all four stores into one 4-deep burst after computing
// all rows in registers (max store MLP into the LSU/L2 queue).
//
// Math (verified 6.8e-5 rel err vs 1e-3 threshold): seed angle = fp32
// product pos*w (same rounding as the JAX reference), 2-term Cody-Waite
// mod-2pi reduction (C1=6.28125 exact in 9 bits -> both FMAs exact;
// residual ~2e-7 rad) + MUFU __sincosf; two independent rotation chains
// (even/odd rows) stepping by the double angle 2w (4 FMA/row, depth 2).

#define D_MODEL 1024
#define THREADS 256                    // thread t owns pair cols 2t, 2t+1
#define ROWS_PER_BLOCK 4
#define ROW_F4  (D_MODEL / 4)          // 256 float4 per row

#define NEG_K2    (-0.02595256324130752f)   // -log2(10000)/512
#define INV_2PI   (0.15915494309189535f)
#define TWO_PI_HI (6.28125f)                // exact in 9 mantissa bits
#define TWO_PI_LO (0.0019353071795864769f)  // 2pi - TWO_PI_HI

__device__ __forceinline__ void sincos_big(float theta, float* s, float* c) {
    // theta in [0, ~8200): 2-term Cody-Waite reduction mod 2pi, then MUFU.
    float n = rintf(theta * INV_2PI);
    float r = fmaf(-n, TWO_PI_HI, theta);
    r = fmaf(-n, TWO_PI_LO, r);
    __sincosf(r, s, c);
}

__global__ __launch_bounds__(THREADS, 8)
void pe_kernel(float4* __restrict__ out, int seq_len) {
    const int t = threadIdx.x;

    // Inverse frequencies (accuracy-critical: each via its own exp2f).
    const float w0 = exp2f((float)(2 * t)     * NEG_K2);
    const float w1 = exp2f((float)(2 * t + 1) * NEG_K2);

    const int row0 = blockIdx.x * ROWS_PER_BLOCK;
    if (row0 >= seq_len) return;

    // Row 0 seed (chain A): fp32 angle product, same as reference.
    float sA0, cA0, sA1, cA1;
    sincos_big((float)row0 * w0, &sA0, &cA0);
    sincos_big((float)row0 * w1, &sA1, &cA1);

    // 1-row step (w <= 1 rad): MUFU path.
    float sw0, cw0, sw1, cw1;
    __sincosf(w0, &sw0, &cw0);
    __sincosf(w1, &sw1, &cw1);

    // Row 1 (chain B) = row 0 rotated by one row.
    float sB0 = fmaf(sA0, cw0,  cA0 * sw0);
    float cB0 = fmaf(cA0, cw0, -sA0 * sw0);
    float sB1 = fmaf(sA1, cw1,  cA1 * sw1);
    float cB1 = fmaf(cA1, cw1, -sA1 * sw1);

    // 2-row step via double-angle: sin2w = 2 sw cw, cos2w = 1 - 2 sw^2.
    const float s20 = 2.0f * sw0 * cw0;
    const float c20 = fmaf(-2.0f * sw0, sw0, 1.0f);
    const float s21 = 2.0f * sw1 * cw1;
    const float c21 = fmaf(-2.0f * sw1, sw1, 1.0f);

    // Rows 2,3 = rows 0,1 rotated by two rows (independent FMA trees).
    float sC0 = fmaf(sA0, c20,  cA0 * s20);
    float cC0 = fmaf(cA0, c20, -sA0 * s20);
    float sC1 = fmaf(sA1, c21,  cA1 * s21);
    float cC1 = fmaf(cA1, c21, -sA1 * s21);
    float sD0 = fmaf(sB0, c20,  cB0 * s20);
    float cD0 = fmaf(cB0, c20, -sB0 * s20);
    float sD1 = fmaf(sB1, c21,  cB1 * s21);
    float cD1 = fmaf(cB1, c21, -sB1 * s21);

    float4* p = out + (size_t)row0 * ROW_F4 + t;

    if (row0 + ROWS_PER_BLOCK <= seq_len) {
        // Front-batched 4-deep store burst (max store MLP, then exit).
        p[0 * ROW_F4] = make_float4(sA0, cA0, sA1, cA1);
        p[1 * ROW_F4] = make_float4(sB0, cB0, sB1, cB1);
        p[2 * ROW_F4] = make_float4(sC0, cC0, sC1, cC1);
        p[3 * ROW_F4] = make_float4(sD0, cD0, sD1, cD1);
    } else {
        // Tail (seq_len not divisible by ROWS_PER_BLOCK).
        const int rows = seq_len - row0;
        if (rows > 0) p[0 * ROW_F4] = make_float4(sA0, cA0, sA1, cA1);
        if (rows > 1) p[1 * ROW_F4] = make_float4(sB0, cB0, sB1, cB1);
        if (rows > 2) p[2 * ROW_F4] = make_float4(sC0, cC0, sC1, cC1);
    }
}

extern "C" void kernel_launch(void* const* d_in, const int* in_sizes, int n_in,
                              void* d_out, int out_size) {
    (void)d_in; (void)in_sizes; (void)n_in;
    const int seq_len = out_size / D_MODEL;    // 8192
    float4* out = (float4*)d_out;

    const int grid = (seq_len + ROWS_PER_BLOCK - 1) / ROWS_PER_BLOCK;  // 2048
    pe_kernel<<<grid, THREADS>>>(out, seq_len);
}